// round 7
// baseline (speedup 1.0000x reference)
#include <cuda_runtime.h>
#include <cuda_fp16.h>
#include <cstdint>
#include <math.h>

// ---------------------------------------------------------------------------
// Problem constants
// ---------------------------------------------------------------------------
#define NBATCH 8
#define NCH    64
#define MAPH   96
#define NBR    8
#define BSTR   104
#define BCHS   (BSTR*BSTR)
#define WSETW  18432            // uint32 fragment words per weight set (9*4*8*64)
#define PIXB   144              // bytes per patch pixel (64ch fp16 + 16B pad)

// ---------------------------------------------------------------------------
// Device-global scratch (channel-last fp16 activations)
// ---------------------------------------------------------------------------
__device__ __align__(16) __half g_x16[(size_t)NBATCH*MAPH*MAPH*NCH];       // [b][pix][ic]
__device__ __align__(16) __half g_buf1[(size_t)NBR*NBATCH*BCHS*NCH];       // [(br,b)][pix][ic]
__device__ __align__(16) __half g_buf2[(size_t)NBR*NBATCH*BCHS*NCH];
__device__ float  g_bmax[NBR*NBATCH*MAPH*MAPH];
__device__ __align__(16) uint32_t g_w1[8*WSETW];   // fp16 B-fragment images
__device__ __align__(16) uint32_t g_w2[4*WSETW];
__device__ __align__(16) uint32_t g_w3[4*WSETW];
__device__ float g_bias[3*64];

// ---------------------------------------------------------------------------
// Helpers
// ---------------------------------------------------------------------------
__device__ __forceinline__ void rotmap(int k, int A, int B, int& sa, int& sb) {
    switch (k & 3) {
        case 0: sa = A;     sb = B;     break;
        case 1: sa = 2 - B; sb = A;     break;
        case 2: sa = 2 - A; sb = 2 - B; break;
        default: sa = B;    sb = 2 - A; break;
    }
}
__device__ __forceinline__ uint32_t smem_u32(const void* p) {
    uint32_t a;
    asm("{ .reg .u64 t; cvta.to.shared.u64 t, %1; cvt.u32.u64 %0, t; }"
        : "=r"(a) : "l"(p));
    return a;
}
__device__ __forceinline__ void mma_f16(float& c0, float& c1, float& c2, float& c3,
                                        uint32_t a0, uint32_t a1, uint32_t a2, uint32_t a3,
                                        uint32_t b0, uint32_t b1) {
    asm volatile(
        "mma.sync.aligned.m16n8k16.row.col.f32.f16.f16.f32 "
        "{%0,%1,%2,%3}, {%4,%5,%6,%7}, {%8,%9}, {%0,%1,%2,%3};"
        : "+f"(c0), "+f"(c1), "+f"(c2), "+f"(c3)
        : "r"(a0), "r"(a1), "r"(a2), "r"(a3), "r"(b0), "r"(b1));
}
__device__ __forceinline__ void ldmatrix_x4(uint32_t& r0, uint32_t& r1,
                                            uint32_t& r2, uint32_t& r3, uint32_t addr) {
    asm volatile("ldmatrix.sync.aligned.m8n8.x4.shared.b16 {%0,%1,%2,%3}, [%4];"
                 : "=r"(r0), "=r"(r1), "=r"(r2), "=r"(r3) : "r"(addr));
}

// ---------------------------------------------------------------------------
// x -> fp16 channel-last transpose: [b][ic][pix] f32 -> [b][pix][ic] f16
// ---------------------------------------------------------------------------
__global__ void cvt_x(const float* __restrict__ x)
{
    __shared__ float t[64][65];
    const int NPB = MAPH * MAPH;                 // 9216
    const int b = blockIdx.x / (NPB / 64);       // 144 tiles per batch
    const int pix0 = (blockIdx.x % (NPB / 64)) * 64;
    const float* src = x + (size_t)b * NCH * NPB;
    for (int i = threadIdx.x; i < 4096; i += 256) {
        int ic = i >> 6, px = i & 63;
        t[px][ic] = src[ic * NPB + pix0 + px];
    }
    __syncthreads();
    __half* dst = g_x16 + ((size_t)b * NPB + pix0) * NCH;
    for (int i = threadIdx.x; i < 4096; i += 256) {
        int px = i >> 6, ic = i & 63;
        dst[px * 64 + ic] = __float2half(t[px][ic]);
    }
}

// ---------------------------------------------------------------------------
// Weight prep: fold BN + rotation + (stage1) channel-roll perm; emit fp16
// B-fragment words for mma.m16n8k16:
//   word idx e = ((tap*4 + k16)*8 + nt)*64 + lane*2 + r
//   halves    = W[oc = nt*8 + lane/4][ic = k16*16 + 2*(lane%4) + 8r + {0,1}]
// ---------------------------------------------------------------------------
__global__ void prep_kernel(
    const float* __restrict__ dcn_w, const float* __restrict__ dcn_b,
    const float* __restrict__ c2w,   const float* __restrict__ c2b,
    const float* __restrict__ c3w,   const float* __restrict__ c3b,
    const float* __restrict__ gam,   const float* __restrict__ bet,
    const float* __restrict__ mu,    const float* __restrict__ va)
{
    int id = blockIdx.x * blockDim.x + threadIdx.x;
    const int W1N = 8 * WSETW, W2N = 4 * WSETW;

    if (id < W1N + 2 * W2N) {
        int setBase;
        uint32_t* dst;
        const float* src;
        int bnOff;
        if (id < W1N)            { dst = g_w1; src = dcn_w; bnOff = 0;   setBase = id; }
        else if (id < W1N + W2N) { dst = g_w2; src = c2w;   bnOff = 64;  setBase = id - W1N; }
        else                     { dst = g_w3; src = c3w;   bnOff = 128; setBase = id - W1N - W2N; }
        int set = setBase / WSETW;
        int e   = setBase % WSETW;
        int r    = e & 1;
        int lane = (e >> 1) & 31;
        int nt   = (e >> 6) & 7;
        int k16  = (e >> 9) & 3;
        int tap  = e >> 11;            // 0..8
        int g  = lane >> 2;
        int t4 = lane & 3;
        int oc  = nt * 8 + g;
        int ic0 = k16 * 16 + 2 * t4 + 8 * r;
        int sa, sb; rotmap(set & 3, tap / 3, tap % 3, sa, sb);
        float scale = gam[bnOff + oc] * rsqrtf(va[bnOff + oc] + 1e-5f);
        int sc0 = (bnOff == 0) ? ((ic0 + 8 * set) & 63) : ic0;
        int sc1 = (bnOff == 0) ? ((ic0 + 1 + 8 * set) & 63) : (ic0 + 1);
        float v0 = src[((oc * 64 + sc0) * 3 + sa) * 3 + sb] * scale;
        float v1 = src[((oc * 64 + sc1) * 3 + sa) * 3 + sb] * scale;
        uint32_t w = (uint32_t)__half_as_ushort(__float2half(v0))
                   | ((uint32_t)__half_as_ushort(__float2half(v1)) << 16);
        dst[setBase] = w;
        return;
    }
    id -= W1N + 2 * W2N;
    if (id < 192) {
        int s = id / 64, oc = id & 63;
        float scale = gam[s * 64 + oc] * rsqrtf(va[s * 64 + oc] + 1e-5f);
        const float* cb = (s == 0) ? dcn_b : ((s == 1) ? c2b : c3b);
        g_bias[id] = cb[oc] * scale + bet[s * 64 + oc] - mu[s * 64 + oc] * scale;
    }
}

// ---------------------------------------------------------------------------
// Conv kernel: fp16 mma.sync.m16n8k16 implicit GEMM, ldmatrix A feeds.
// Block = 128 threads = 4 warps (warpM 0..3), 2 CTAs/SM.
// Pixel tile = 128 px (8 rows x 16 cols). Warp tile = 32 px x 64 oc
// (mt=2, nt=8): smem bytes/MMA = 512/8 + 256/2 = 192.
// K = 576 as 9 taps x 4 k16-blocks.
// ---------------------------------------------------------------------------
template<int D, int STAGE>
__global__ void __launch_bounds__(128, 2)
conv_mma()
{
    constexpr int R = 8 + 2 * D;          // patch rows
    constexpr int C = 16 + 2 * D;         // patch cols
    constexpr int NPIX = R * C;

    extern __shared__ char sm[];
    uint32_t* sW    = (uint32_t*)sm;                       // 73728B
    __half*   sIn   = (__half*)(sm + 73728);               // NPIX * 144B
    float*    sBias = (float*)(sm + 73728 + NPIX * PIXB);  // 64

    const int tid  = threadIdx.x;
    const int lane = tid & 31;
    const int warpM = tid >> 5;           // 0..3

    const int br = blockIdx.z;
    const int b  = blockIdx.y;
    const int odd = br & 1;

    int pad, inValid, outH;
    if (STAGE == 1)      { pad = odd ? 5 : 1; inValid = 96;             outH = odd ? 104 : 96; }
    else if (STAGE == 2) { pad = odd ? 0 : 2; inValid = odd ? 104 : 96; outH = odd ? 100 : 96; }
    else                 { pad = odd ? 0 : 2; inValid = odd ? 100 : 96; outH = 96; }
    const int outW = outH;
    const int rowTiles = (outH + 7) >> 3;
    const int colTiles = (outW + 15) >> 4;
    const int rowTile = blockIdx.x;
    if (rowTile >= rowTiles) return;      // uniform per block

    const int srcStride = (STAGE == 1) ? MAPH : BSTR;
    const __half* inp = (STAGE == 1) ? (g_x16 + (size_t)b * MAPH * MAPH * NCH)
                       : (STAGE == 2) ? (g_buf1 + (size_t)(br * NBATCH + b) * BCHS * NCH)
                                      : (g_buf2 + (size_t)(br * NBATCH + b) * BCHS * NCH);
    __half* outp = ((STAGE == 1) ? g_buf1 : g_buf2)
                   + (size_t)(br * NBATCH + b) * BCHS * NCH;
    const uint32_t* wsrc = (STAGE == 1) ? (g_w1 + br * WSETW)
                          : (STAGE == 2) ? (g_w2 + (br & 3) * WSETW)
                                         : (g_w3 + (br & 3) * WSETW);

    // ---- stage weights (fragment words, linear copy) + bias ----
    {
        uint4* wd = (uint4*)sW;
        const uint4* ws = (const uint4*)wsrc;
        #pragma unroll 4
        for (int i = tid; i < WSETW / 4; i += 128) wd[i] = ws[i];
        if (tid < 64) sBias[tid] = g_bias[(STAGE - 1) * 64 + tid];
    }

    const int rowBase = rowTile * 8;
    const int g  = lane >> 2;
    const int t4 = lane & 3;

    // ldmatrix per-lane base: pixel col = lane&15, k-half-block = lane>>4
    const uint32_t sInU = smem_u32(sIn);
    const uint32_t aLane = sInU + ((warpM * 2) * C + (lane & 15)) * PIXB + (lane >> 4) * 16;

    uint4* sInV = (uint4*)sIn;
    const uint4* srcV = (const uint4*)inp;

    for (int ct = 0; ct < colTiles; ct++) {
        const int colBase = ct * 16;
        __syncthreads();   // prior-iter reads of sIn done before overwrite

        // ---- patch copy: vectorized channel-last (8 uint4 per pixel) ----
        for (int i = tid; i < NPIX * 8; i += 128) {
            int w   = i & 7;
            int pix = i >> 3;
            int r = pix / C;
            int c = pix - r * C;
            int gy = rowBase + r - pad;
            int gx = colBase + c - pad;
            uint4 v = make_uint4(0u, 0u, 0u, 0u);
            if ((unsigned)gy < (unsigned)inValid && (unsigned)gx < (unsigned)inValid)
                v = srcV[(size_t)(gy * srcStride + gx) * 8 + w];
            sInV[pix * 9 + w] = v;
        }
        __syncthreads();

        // ---- GEMM: 128px x 64oc x 576; warp = 32px x 64oc ----
        float acc[2][8][4];
        #pragma unroll
        for (int mt = 0; mt < 2; mt++)
            #pragma unroll
            for (int nt = 0; nt < 8; nt++)
                #pragma unroll
                for (int q = 0; q < 4; q++) acc[mt][nt][q] = 0.f;

        #pragma unroll 1
        for (int tap = 0; tap < 9; tap++) {
            const int dy = (tap / 3) * D, dx = (tap % 3) * D;
            const uint32_t aT0 = aLane + (dy * C + dx) * PIXB;
            const uint32_t aT1 = aT0 + C * PIXB;
            const uint2* pB = (const uint2*)sW + (tap * 4) * 8 * 32 + lane;

            #pragma unroll
            for (int k16 = 0; k16 < 4; k16++) {
                uint32_t a00, a01, a02, a03, a10, a11, a12, a13;
                ldmatrix_x4(a00, a01, a02, a03, aT0 + k16 * 32);
                ldmatrix_x4(a10, a11, a12, a13, aT1 + k16 * 32);
                const uint2* pBk = pB + k16 * 256;
                #pragma unroll
                for (int nt = 0; nt < 8; nt++) {
                    uint2 bb = pBk[nt * 32];
                    mma_f16(acc[0][nt][0], acc[0][nt][1], acc[0][nt][2], acc[0][nt][3],
                            a00, a01, a02, a03, bb.x, bb.y);
                    mma_f16(acc[1][nt][0], acc[1][nt][1], acc[1][nt][2], acc[1][nt][3],
                            a10, a11, a12, a13, bb.x, bb.y);
                }
            }
        }

        // ---- epilogue ----
        if (STAGE < 3) {
            #pragma unroll
            for (int mt = 0; mt < 2; mt++) {
                const int oy = rowBase + warpM * 2 + mt;
                const int ox0 = colBase + g;
                const int ox1 = ox0 + 8;
                if (oy < outH) {
                    #pragma unroll
                    for (int nt = 0; nt < 8; nt++) {
                        const int oc = nt * 8 + 2 * t4;
                        const float b0 = sBias[oc], b1 = sBias[oc + 1];
                        if (ox0 < outW) {
                            float2 f = make_float2(fmaxf(acc[mt][nt][0] + b0, 0.f),
                                                   fmaxf(acc[mt][nt][1] + b1, 0.f));
                            *(__half2*)(outp + (size_t)(oy * BSTR + ox0) * 64 + oc) =
                                __float22half2_rn(f);
                        }
                        if (ox1 < outW) {
                            float2 f = make_float2(fmaxf(acc[mt][nt][2] + b0, 0.f),
                                                   fmaxf(acc[mt][nt][3] + b1, 0.f));
                            *(__half2*)(outp + (size_t)(oy * BSTR + ox1) * 64 + oc) =
                                __float22half2_rn(f);
                        }
                    }
                }
            }
        } else {
            // bias + relu + channel-max entirely in-warp (warp owns all 64 oc)
            float* bm = g_bmax + (size_t)(br * NBATCH + b) * MAPH * MAPH;
            #pragma unroll
            for (int mt = 0; mt < 2; mt++) {
                float v0 = 0.f, v1 = 0.f;
                #pragma unroll
                for (int nt = 0; nt < 8; nt++) {
                    const int oc = nt * 8 + 2 * t4;
                    const float b0 = sBias[oc], b1 = sBias[oc + 1];
                    v0 = fmaxf(v0, fmaxf(acc[mt][nt][0] + b0, acc[mt][nt][1] + b1));
                    v1 = fmaxf(v1, fmaxf(acc[mt][nt][2] + b0, acc[mt][nt][3] + b1));
                }
                v0 = fmaxf(v0, __shfl_xor_sync(0xFFFFFFFF, v0, 1));
                v0 = fmaxf(v0, __shfl_xor_sync(0xFFFFFFFF, v0, 2));
                v1 = fmaxf(v1, __shfl_xor_sync(0xFFFFFFFF, v1, 1));
                v1 = fmaxf(v1, __shfl_xor_sync(0xFFFFFFFF, v1, 2));
                if (t4 == 0) {
                    const int oy = rowBase + warpM * 2 + mt;   // stage3: exact tiling
                    bm[oy * MAPH + colBase + g]     = v0;
                    bm[oy * MAPH + colBase + g + 8] = v1;
                }
            }
        }
    }
}

// ---------------------------------------------------------------------------
// Cross-branch max + sigmoid + clip
// ---------------------------------------------------------------------------
__global__ void final_k(float* __restrict__ out)
{
    int i = blockIdx.x * blockDim.x + threadIdx.x;
    const int NPB = MAPH * MAPH;
    if (i >= NBATCH * NPB) return;
    int b = i / NPB, p = i - b * NPB;
    float m = g_bmax[b * NPB + p];
    #pragma unroll
    for (int br = 1; br < NBR; br++)
        m = fmaxf(m, g_bmax[(br * NBATCH + b) * NPB + p]);
    float s = 1.f / (1.f + expf(-m));
    out[i] = fminf(fmaxf(s, 0.0001f), 0.9999f);
}

// ---------------------------------------------------------------------------
// Launch
// ---------------------------------------------------------------------------
extern "C" void kernel_launch(void* const* d_in, const int* in_sizes, int n_in,
                              void* d_out, int out_size)
{
    const float* x     = (const float*)d_in[0];
    const float* dcn_w = (const float*)d_in[2];
    const float* dcn_b = (const float*)d_in[3];
    const float* c2w   = (const float*)d_in[4];
    const float* c2b   = (const float*)d_in[5];
    const float* c3w   = (const float*)d_in[6];
    const float* c3b   = (const float*)d_in[7];
    const float* gam   = (const float*)d_in[8];
    const float* bet   = (const float*)d_in[9];
    const float* mu    = (const float*)d_in[10];
    const float* va    = (const float*)d_in[11];

    constexpr int SMEM_D1 = 73728 + 10 * 18 * PIXB + 64 * 4;  // 99904
    constexpr int SMEM_D2 = 73728 + 12 * 20 * PIXB + 64 * 4;  // 108544

    cudaFuncSetAttribute((const void*)conv_mma<1, 1>,
                         cudaFuncAttributeMaxDynamicSharedMemorySize, SMEM_D1);
    cudaFuncSetAttribute((const void*)conv_mma<2, 2>,
                         cudaFuncAttributeMaxDynamicSharedMemorySize, SMEM_D2);
    cudaFuncSetAttribute((const void*)conv_mma<2, 3>,
                         cudaFuncAttributeMaxDynamicSharedMemorySize, SMEM_D2);

    cvt_x<<<NBATCH * (MAPH * MAPH / 64), 256>>>(x);

    const int prepN = 16 * WSETW + 192;
    prep_kernel<<<(prepN + 255) / 256, 256>>>(dcn_w, dcn_b, c2w, c2b, c3w, c3b,
                                              gam, bet, mu, va);

    // Stage 1 (D=1): even 96->96 (pad1), odd 96->104 (halo 5). max rowTiles = 13
    conv_mma<1, 1><<<dim3(13, NBATCH, NBR), 128, SMEM_D1>>>();
    // Stage 2 (D=2): even 96->96 (pad2), odd 104->100 (valid). max rowTiles = 13
    conv_mma<2, 2><<<dim3(13, NBATCH, NBR), 128, SMEM_D2>>>();
    // Stage 3 (D=2) + channel max: even 96->96, odd 100->96. rowTiles = 12
    conv_mma<2, 3><<<dim3(12, NBATCH, NBR), 128, SMEM_D2>>>();

    final_k<<<(NBATCH * MAPH * MAPH + 255) / 256, 256>>>((float*)d_out);
}

// round 8
// speedup vs baseline: 1.0102x; 1.0102x over previous
#include <cuda_runtime.h>
#include <cuda_fp16.h>
#include <cstdint>
#include <math.h>

// ---------------------------------------------------------------------------
// Problem constants
// ---------------------------------------------------------------------------
#define NBATCH 8
#define NCH    64
#define MAPH   96
#define NBR    8
#define BSTR   104
#define BCHS   (BSTR*BSTR)
#define WSETW  18432            // uint32 fragment words per weight set (9*4*8*64)
#define PIXB   144              // bytes per patch pixel (64ch fp16 + 16B pad)
#define STAGEB 32768            // fp32 staging bytes (4 warps * 32 lanes * 64 * 4)

// ---------------------------------------------------------------------------
// Device-global scratch (channel-last fp16 activations)
// ---------------------------------------------------------------------------
__device__ __align__(16) __half g_x16[(size_t)NBATCH*MAPH*MAPH*NCH];       // [b][pix][ic]
__device__ __align__(16) __half g_buf1[(size_t)NBR*NBATCH*BCHS*NCH];       // [(br,b)][pix][ic]
__device__ __align__(16) __half g_buf2[(size_t)NBR*NBATCH*BCHS*NCH];
__device__ float  g_bmax[NBR*NBATCH*MAPH*MAPH];
__device__ __align__(16) uint32_t g_w1[8*WSETW];   // fp16 B-fragment images
__device__ __align__(16) uint32_t g_w2[4*WSETW];
__device__ __align__(16) uint32_t g_w3[4*WSETW];
__device__ float g_bias[3*64];

// ---------------------------------------------------------------------------
// Helpers
// ---------------------------------------------------------------------------
__device__ __forceinline__ void rotmap(int k, int A, int B, int& sa, int& sb) {
    switch (k & 3) {
        case 0: sa = A;     sb = B;     break;
        case 1: sa = 2 - B; sb = A;     break;
        case 2: sa = 2 - A; sb = 2 - B; break;
        default: sa = B;    sb = 2 - A; break;
    }
}
__device__ __forceinline__ uint32_t smem_u32(const void* p) {
    uint32_t a;
    asm("{ .reg .u64 t; cvta.to.shared.u64 t, %1; cvt.u32.u64 %0, t; }"
        : "=r"(a) : "l"(p));
    return a;
}
__device__ __forceinline__ void mma_f16(float& c0, float& c1, float& c2, float& c3,
                                        uint32_t a0, uint32_t a1, uint32_t a2, uint32_t a3,
                                        uint32_t b0, uint32_t b1) {
    asm volatile(
        "mma.sync.aligned.m16n8k16.row.col.f32.f16.f16.f32 "
        "{%0,%1,%2,%3}, {%4,%5,%6,%7}, {%8,%9}, {%0,%1,%2,%3};"
        : "+f"(c0), "+f"(c1), "+f"(c2), "+f"(c3)
        : "r"(a0), "r"(a1), "r"(a2), "r"(a3), "r"(b0), "r"(b1));
}
__device__ __forceinline__ void ldmatrix_x4(uint32_t& r0, uint32_t& r1,
                                            uint32_t& r2, uint32_t& r3, uint32_t addr) {
    asm volatile("ldmatrix.sync.aligned.m8n8.x4.shared.b16 {%0,%1,%2,%3}, [%4];"
                 : "=r"(r0), "=r"(r1), "=r"(r2), "=r"(r3) : "r"(addr));
}

// ---------------------------------------------------------------------------
// x -> fp16 channel-last transpose: [b][ic][pix] f32 -> [b][pix][ic] f16
// ---------------------------------------------------------------------------
__global__ void cvt_x(const float* __restrict__ x)
{
    __shared__ float t[64][65];
    const int NPB = MAPH * MAPH;                 // 9216
    const int b = blockIdx.x / (NPB / 64);       // 144 tiles per batch
    const int pix0 = (blockIdx.x % (NPB / 64)) * 64;
    const float* src = x + (size_t)b * NCH * NPB;
    for (int i = threadIdx.x; i < 4096; i += 256) {
        int ic = i >> 6, px = i & 63;
        t[px][ic] = src[ic * NPB + pix0 + px];
    }
    __syncthreads();
    __half* dst = g_x16 + ((size_t)b * NPB + pix0) * NCH;
    for (int i = threadIdx.x; i < 4096; i += 256) {
        int px = i >> 6, ic = i & 63;
        dst[px * 64 + ic] = __float2half(t[px][ic]);
    }
}

// ---------------------------------------------------------------------------
// Weight prep: fold BN + rotation + (stage1) channel-roll perm; emit fp16
// B-fragment words for mma.m16n8k16:
//   word idx e = ((tap*4 + k16)*8 + nt)*64 + lane*2 + r
//   halves    = W[oc = nt*8 + lane/4][ic = k16*16 + 2*(lane%4) + 8r + {0,1}]
// ---------------------------------------------------------------------------
__global__ void prep_kernel(
    const float* __restrict__ dcn_w, const float* __restrict__ dcn_b,
    const float* __restrict__ c2w,   const float* __restrict__ c2b,
    const float* __restrict__ c3w,   const float* __restrict__ c3b,
    const float* __restrict__ gam,   const float* __restrict__ bet,
    const float* __restrict__ mu,    const float* __restrict__ va)
{
    int id = blockIdx.x * blockDim.x + threadIdx.x;
    const int W1N = 8 * WSETW, W2N = 4 * WSETW;

    if (id < W1N + 2 * W2N) {
        int setBase;
        uint32_t* dst;
        const float* src;
        int bnOff;
        if (id < W1N)            { dst = g_w1; src = dcn_w; bnOff = 0;   setBase = id; }
        else if (id < W1N + W2N) { dst = g_w2; src = c2w;   bnOff = 64;  setBase = id - W1N; }
        else                     { dst = g_w3; src = c3w;   bnOff = 128; setBase = id - W1N - W2N; }
        int set = setBase / WSETW;
        int e   = setBase % WSETW;
        int r    = e & 1;
        int lane = (e >> 1) & 31;
        int nt   = (e >> 6) & 7;
        int k16  = (e >> 9) & 3;
        int tap  = e >> 11;            // 0..8
        int g  = lane >> 2;
        int t4 = lane & 3;
        int oc  = nt * 8 + g;
        int ic0 = k16 * 16 + 2 * t4 + 8 * r;
        int sa, sb; rotmap(set & 3, tap / 3, tap % 3, sa, sb);
        float scale = gam[bnOff + oc] * rsqrtf(va[bnOff + oc] + 1e-5f);
        int sc0 = (bnOff == 0) ? ((ic0 + 8 * set) & 63) : ic0;
        int sc1 = (bnOff == 0) ? ((ic0 + 1 + 8 * set) & 63) : (ic0 + 1);
        float v0 = src[((oc * 64 + sc0) * 3 + sa) * 3 + sb] * scale;
        float v1 = src[((oc * 64 + sc1) * 3 + sa) * 3 + sb] * scale;
        uint32_t w = (uint32_t)__half_as_ushort(__float2half(v0))
                   | ((uint32_t)__half_as_ushort(__float2half(v1)) << 16);
        dst[setBase] = w;
        return;
    }
    id -= W1N + 2 * W2N;
    if (id < 192) {
        int s = id / 64, oc = id & 63;
        float scale = gam[s * 64 + oc] * rsqrtf(va[s * 64 + oc] + 1e-5f);
        const float* cb = (s == 0) ? dcn_b : ((s == 1) ? c2b : c3b);
        g_bias[id] = cb[oc] * scale + bet[s * 64 + oc] - mu[s * 64 + oc] * scale;
    }
}

// ---------------------------------------------------------------------------
// Conv kernel: fp16 mma.sync.m16n8k16 implicit GEMM, split-K over k16.
// Block = 256 threads = 8 warps: warpK (wid>>2) x warpM (wid&3); 2 CTAs/SM.
// Pixel tile = 128 px (8 rows x 16 cols). Warp tile = 32 px x 64 oc over
// half of K (9 taps x 2 k16): smem bytes/MMA = 512/8 + 256/2 = 192.
// warpK1 stages fp32 accs into SMEM (aliases dead patch), warpK0 adds +
// runs epilogue.
// ---------------------------------------------------------------------------
template<int D, int STAGE>
__global__ void __launch_bounds__(256, 2)
conv_mma()
{
    constexpr int R = 8 + 2 * D;          // patch rows
    constexpr int C = 16 + 2 * D;         // patch cols
    constexpr int NPIX = R * C;
    constexpr int PATB = (NPIX * PIXB > STAGEB) ? NPIX * PIXB : STAGEB;

    extern __shared__ char sm[];
    uint32_t* sW    = (uint32_t*)sm;                 // 73728B
    __half*   sIn   = (__half*)(sm + 73728);         // patch (also fp32 staging alias)
    float*    sStage = (float*)(sm + 73728);         // 32KB staging
    float*    sBias = (float*)(sm + 73728 + PATB);   // 64

    const int tid  = threadIdx.x;
    const int lane = tid & 31;
    const int wid  = tid >> 5;
    const int warpM = wid & 3;            // 0..3
    const int warpK = wid >> 2;           // 0/1
    const int wtid128 = tid & 127;        // lane id within K-half (matches peer)

    const int br = blockIdx.z;
    const int b  = blockIdx.y;
    const int odd = br & 1;

    int pad, inValid, outH;
    if (STAGE == 1)      { pad = odd ? 5 : 1; inValid = 96;             outH = odd ? 104 : 96; }
    else if (STAGE == 2) { pad = odd ? 0 : 2; inValid = odd ? 104 : 96; outH = odd ? 100 : 96; }
    else                 { pad = odd ? 0 : 2; inValid = odd ? 100 : 96; outH = 96; }
    const int outW = outH;
    const int rowTiles = (outH + 7) >> 3;
    const int colTiles = (outW + 15) >> 4;
    const int rowTile = blockIdx.x;
    if (rowTile >= rowTiles) return;      // uniform per block

    const int srcStride = (STAGE == 1) ? MAPH : BSTR;
    const __half* inp = (STAGE == 1) ? (g_x16 + (size_t)b * MAPH * MAPH * NCH)
                       : (STAGE == 2) ? (g_buf1 + (size_t)(br * NBATCH + b) * BCHS * NCH)
                                      : (g_buf2 + (size_t)(br * NBATCH + b) * BCHS * NCH);
    __half* outp = ((STAGE == 1) ? g_buf1 : g_buf2)
                   + (size_t)(br * NBATCH + b) * BCHS * NCH;
    const uint32_t* wsrc = (STAGE == 1) ? (g_w1 + br * WSETW)
                          : (STAGE == 2) ? (g_w2 + (br & 3) * WSETW)
                                         : (g_w3 + (br & 3) * WSETW);

    // ---- stage weights (fragment words, linear copy) + bias ----
    {
        uint4* wd = (uint4*)sW;
        const uint4* ws = (const uint4*)wsrc;
        #pragma unroll 4
        for (int i = tid; i < WSETW / 4; i += 256) wd[i] = ws[i];
        if (tid < 64) sBias[tid] = g_bias[(STAGE - 1) * 64 + tid];
    }

    const int rowBase = rowTile * 8;
    const int g  = lane >> 2;
    const int t4 = lane & 3;
    const int kbase = warpK * 2;          // k16 offset for this K-half

    // ldmatrix per-lane base: pixel col = lane&15, k-half-block = lane>>4
    const uint32_t sInU = smem_u32(sIn);
    const uint32_t aLane = sInU + ((warpM * 2) * C + (lane & 15)) * PIXB + (lane >> 4) * 16;

    uint4* sInV = (uint4*)sIn;
    const uint4* srcV = (const uint4*)inp;

    for (int ct = 0; ct < colTiles; ct++) {
        const int colBase = ct * 16;
        __syncthreads();   // staging reads (prev iter) done before patch overwrite

        // ---- patch copy: vectorized channel-last (8 uint4 per pixel) ----
        for (int i = tid; i < NPIX * 8; i += 256) {
            int w   = i & 7;
            int pix = i >> 3;
            int r = pix / C;
            int c = pix - r * C;
            int gy = rowBase + r - pad;
            int gx = colBase + c - pad;
            uint4 v = make_uint4(0u, 0u, 0u, 0u);
            if ((unsigned)gy < (unsigned)inValid && (unsigned)gx < (unsigned)inValid)
                v = srcV[(size_t)(gy * srcStride + gx) * 8 + w];
            sInV[pix * 9 + w] = v;
        }
        __syncthreads();

        // ---- GEMM: 128px x 64oc x 288 (this warp's K-half) ----
        float acc[2][8][4];
        #pragma unroll
        for (int mt = 0; mt < 2; mt++)
            #pragma unroll
            for (int nt = 0; nt < 8; nt++)
                #pragma unroll
                for (int q = 0; q < 4; q++) acc[mt][nt][q] = 0.f;

        #pragma unroll 1
        for (int tap = 0; tap < 9; tap++) {
            const int dy = (tap / 3) * D, dx = (tap % 3) * D;
            const uint32_t aT0 = aLane + (dy * C + dx) * PIXB;
            const uint32_t aT1 = aT0 + C * PIXB;
            const uint2* pB = (const uint2*)sW + (tap * 4 + kbase) * 8 * 32 + lane;

            #pragma unroll
            for (int k16 = 0; k16 < 2; k16++) {
                uint32_t a00, a01, a02, a03, a10, a11, a12, a13;
                ldmatrix_x4(a00, a01, a02, a03, aT0 + (kbase + k16) * 32);
                ldmatrix_x4(a10, a11, a12, a13, aT1 + (kbase + k16) * 32);
                const uint2* pBk = pB + k16 * 256;
                #pragma unroll
                for (int nt = 0; nt < 8; nt++) {
                    uint2 bb = pBk[nt * 32];
                    mma_f16(acc[0][nt][0], acc[0][nt][1], acc[0][nt][2], acc[0][nt][3],
                            a00, a01, a02, a03, bb.x, bb.y);
                    mma_f16(acc[1][nt][0], acc[1][nt][1], acc[1][nt][2], acc[1][nt][3],
                            a10, a11, a12, a13, bb.x, bb.y);
                }
            }
        }

        // ---- cross-K reduction: warpK1 -> fp32 staging (aliases patch) ----
        __syncthreads();   // all ldmatrix reads of patch done
        if (warpK == 1) {
            #pragma unroll
            for (int mt = 0; mt < 2; mt++)
                #pragma unroll
                for (int nt = 0; nt < 8; nt++)
                    #pragma unroll
                    for (int q = 0; q < 4; q++)
                        sStage[(mt * 32 + nt * 4 + q) * 128 + wtid128] = acc[mt][nt][q];
        }
        __syncthreads();

        if (warpK == 0) {
            #pragma unroll
            for (int mt = 0; mt < 2; mt++)
                #pragma unroll
                for (int nt = 0; nt < 8; nt++)
                    #pragma unroll
                    for (int q = 0; q < 4; q++)
                        acc[mt][nt][q] += sStage[(mt * 32 + nt * 4 + q) * 128 + wtid128];

            // ---- epilogue (warpK0 only; warp owns all 64 oc of its pixels) ----
            if (STAGE < 3) {
                #pragma unroll
                for (int mt = 0; mt < 2; mt++) {
                    const int oy = rowBase + warpM * 2 + mt;
                    const int ox0 = colBase + g;
                    const int ox1 = ox0 + 8;
                    if (oy < outH) {
                        #pragma unroll
                        for (int nt = 0; nt < 8; nt++) {
                            const int oc = nt * 8 + 2 * t4;
                            const float b0 = sBias[oc], b1 = sBias[oc + 1];
                            if (ox0 < outW) {
                                float2 f = make_float2(fmaxf(acc[mt][nt][0] + b0, 0.f),
                                                       fmaxf(acc[mt][nt][1] + b1, 0.f));
                                *(__half2*)(outp + (size_t)(oy * BSTR + ox0) * 64 + oc) =
                                    __float22half2_rn(f);
                            }
                            if (ox1 < outW) {
                                float2 f = make_float2(fmaxf(acc[mt][nt][2] + b0, 0.f),
                                                       fmaxf(acc[mt][nt][3] + b1, 0.f));
                                *(__half2*)(outp + (size_t)(oy * BSTR + ox1) * 64 + oc) =
                                    __float22half2_rn(f);
                            }
                        }
                    }
                }
            } else {
                float* bm = g_bmax + (size_t)(br * NBATCH + b) * MAPH * MAPH;
                #pragma unroll
                for (int mt = 0; mt < 2; mt++) {
                    float v0 = 0.f, v1 = 0.f;
                    #pragma unroll
                    for (int nt = 0; nt < 8; nt++) {
                        const int oc = nt * 8 + 2 * t4;
                        const float b0 = sBias[oc], b1 = sBias[oc + 1];
                        v0 = fmaxf(v0, fmaxf(acc[mt][nt][0] + b0, acc[mt][nt][1] + b1));
                        v1 = fmaxf(v1, fmaxf(acc[mt][nt][2] + b0, acc[mt][nt][3] + b1));
                    }
                    v0 = fmaxf(v0, __shfl_xor_sync(0xFFFFFFFF, v0, 1));
                    v0 = fmaxf(v0, __shfl_xor_sync(0xFFFFFFFF, v0, 2));
                    v1 = fmaxf(v1, __shfl_xor_sync(0xFFFFFFFF, v1, 1));
                    v1 = fmaxf(v1, __shfl_xor_sync(0xFFFFFFFF, v1, 2));
                    if (t4 == 0) {
                        const int oy = rowBase + warpM * 2 + mt;   // stage3: exact tiling
                        bm[oy * MAPH + colBase + g]     = v0;
                        bm[oy * MAPH + colBase + g + 8] = v1;
                    }
                }
            }
        }
    }
}

// ---------------------------------------------------------------------------
// Cross-branch max + sigmoid + clip
// ---------------------------------------------------------------------------
__global__ void final_k(float* __restrict__ out)
{
    int i = blockIdx.x * blockDim.x + threadIdx.x;
    const int NPB = MAPH * MAPH;
    if (i >= NBATCH * NPB) return;
    int b = i / NPB, p = i - b * NPB;
    float m = g_bmax[b * NPB + p];
    #pragma unroll
    for (int br = 1; br < NBR; br++)
        m = fmaxf(m, g_bmax[(br * NBATCH + b) * NPB + p]);
    float s = 1.f / (1.f + expf(-m));
    out[i] = fminf(fmaxf(s, 0.0001f), 0.9999f);
}

// ---------------------------------------------------------------------------
// Launch
// ---------------------------------------------------------------------------
extern "C" void kernel_launch(void* const* d_in, const int* in_sizes, int n_in,
                              void* d_out, int out_size)
{
    const float* x     = (const float*)d_in[0];
    const float* dcn_w = (const float*)d_in[2];
    const float* dcn_b = (const float*)d_in[3];
    const float* c2w   = (const float*)d_in[4];
    const float* c2b   = (const float*)d_in[5];
    const float* c3w   = (const float*)d_in[6];
    const float* c3b   = (const float*)d_in[7];
    const float* gam   = (const float*)d_in[8];
    const float* bet   = (const float*)d_in[9];
    const float* mu    = (const float*)d_in[10];
    const float* va    = (const float*)d_in[11];

    // patch region padded to >= 32KB for fp32 staging alias
    constexpr int PATB1 = (10 * 18 * PIXB > STAGEB) ? 10 * 18 * PIXB : STAGEB;
    constexpr int PATB2 = (12 * 20 * PIXB > STAGEB) ? 12 * 20 * PIXB : STAGEB;
    constexpr int SMEM_D1 = 73728 + PATB1 + 64 * 4;  // 106,752
    constexpr int SMEM_D2 = 73728 + PATB2 + 64 * 4;  // 108,544

    cudaFuncSetAttribute((const void*)conv_mma<1, 1>,
                         cudaFuncAttributeMaxDynamicSharedMemorySize, SMEM_D1);
    cudaFuncSetAttribute((const void*)conv_mma<2, 2>,
                         cudaFuncAttributeMaxDynamicSharedMemorySize, SMEM_D2);
    cudaFuncSetAttribute((const void*)conv_mma<2, 3>,
                         cudaFuncAttributeMaxDynamicSharedMemorySize, SMEM_D2);

    cvt_x<<<NBATCH * (MAPH * MAPH / 64), 256>>>(x);

    const int prepN = 16 * WSETW + 192;
    prep_kernel<<<(prepN + 255) / 256, 256>>>(dcn_w, dcn_b, c2w, c2b, c3w, c3b,
                                              gam, bet, mu, va);

    // Stage 1 (D=1): even 96->96 (pad1), odd 96->104 (halo 5). max rowTiles = 13
    conv_mma<1, 1><<<dim3(13, NBATCH, NBR), 256, SMEM_D1>>>();
    // Stage 2 (D=2): even 96->96 (pad2), odd 104->100 (valid). max rowTiles = 13
    conv_mma<2, 2><<<dim3(13, NBATCH, NBR), 256, SMEM_D2>>>();
    // Stage 3 (D=2) + channel max: even 96->96, odd 100->96. rowTiles = 12
    conv_mma<2, 3><<<dim3(12, NBATCH, NBR), 256, SMEM_D2>>>();

    final_k<<<(NBATCH * MAPH * MAPH + 255) / 256, 256>>>((float*)d_out);
}

// round 9
// speedup vs baseline: 1.0915x; 1.0805x over previous
#include <cuda_runtime.h>
#include <cuda_fp16.h>
#include <cstdint>
#include <math.h>

// ---------------------------------------------------------------------------
// Problem constants
// ---------------------------------------------------------------------------
#define NBATCH 8
#define NCH    64
#define MAPH   96
#define NBR    8
#define BSTR   104
#define BCHS   (BSTR*BSTR)
#define WSETW  18432            // uint32 fragment words per weight set (9*4*4*128)
#define PIXB   144              // bytes per patch pixel (64ch fp16 + 16B pad)

// ---------------------------------------------------------------------------
// Device-global scratch (channel-last fp16 activations)
// ---------------------------------------------------------------------------
__device__ __align__(16) __half g_x16[(size_t)NBATCH*MAPH*MAPH*NCH];       // [b][pix][ic]
__device__ __align__(16) __half g_buf1[(size_t)NBR*NBATCH*BCHS*NCH];       // [(br,b)][pix][ic]
__device__ __align__(16) __half g_buf2[(size_t)NBR*NBATCH*BCHS*NCH];
__device__ float  g_bmax[NBR*NBATCH*MAPH*MAPH];
__device__ __align__(16) uint32_t g_w1[8*WSETW];   // fp16 B-fragment images
__device__ __align__(16) uint32_t g_w2[4*WSETW];
__device__ __align__(16) uint32_t g_w3[4*WSETW];
__device__ float g_bias[3*64];

// ---------------------------------------------------------------------------
// Helpers
// ---------------------------------------------------------------------------
__device__ __forceinline__ void rotmap(int k, int A, int B, int& sa, int& sb) {
    switch (k & 3) {
        case 0: sa = A;     sb = B;     break;
        case 1: sa = 2 - B; sb = A;     break;
        case 2: sa = 2 - A; sb = 2 - B; break;
        default: sa = B;    sb = 2 - A; break;
    }
}
__device__ __forceinline__ uint32_t smem_u32(const void* p) {
    uint32_t a;
    asm("{ .reg .u64 t; cvta.to.shared.u64 t, %1; cvt.u32.u64 %0, t; }"
        : "=r"(a) : "l"(p));
    return a;
}
__device__ __forceinline__ void mma_f16(float& c0, float& c1, float& c2, float& c3,
                                        uint32_t a0, uint32_t a1, uint32_t a2, uint32_t a3,
                                        uint32_t b0, uint32_t b1) {
    asm volatile(
        "mma.sync.aligned.m16n8k16.row.col.f32.f16.f16.f32 "
        "{%0,%1,%2,%3}, {%4,%5,%6,%7}, {%8,%9}, {%0,%1,%2,%3};"
        : "+f"(c0), "+f"(c1), "+f"(c2), "+f"(c3)
        : "r"(a0), "r"(a1), "r"(a2), "r"(a3), "r"(b0), "r"(b1));
}
__device__ __forceinline__ void ldmatrix_x4(uint32_t& r0, uint32_t& r1,
                                            uint32_t& r2, uint32_t& r3, uint32_t addr) {
    asm volatile("ldmatrix.sync.aligned.m8n8.x4.shared.b16 {%0,%1,%2,%3}, [%4];"
                 : "=r"(r0), "=r"(r1), "=r"(r2), "=r"(r3) : "r"(addr));
}
__device__ __forceinline__ void cp_async16(uint32_t saddr, const void* gaddr, int srcsz) {
    asm volatile("cp.async.cg.shared.global [%0], [%1], 16, %2;"
                 :: "r"(saddr), "l"(gaddr), "r"(srcsz) : "memory");
}

// ---------------------------------------------------------------------------
// x -> fp16 channel-last transpose: [b][ic][pix] f32 -> [b][pix][ic] f16
// ---------------------------------------------------------------------------
__global__ void cvt_x(const float* __restrict__ x)
{
    __shared__ float t[64][65];
    const int NPB = MAPH * MAPH;                 // 9216
    const int b = blockIdx.x / (NPB / 64);       // 144 tiles per batch
    const int pix0 = (blockIdx.x % (NPB / 64)) * 64;
    const float* src = x + (size_t)b * NCH * NPB;
    for (int i = threadIdx.x; i < 4096; i += 256) {
        int ic = i >> 6, px = i & 63;
        t[px][ic] = src[ic * NPB + pix0 + px];
    }
    __syncthreads();
    __half* dst = g_x16 + ((size_t)b * NPB + pix0) * NCH;
    for (int i = threadIdx.x; i < 4096; i += 256) {
        int px = i >> 6, ic = i & 63;
        dst[px * 64 + ic] = __float2half(t[px][ic]);
    }
}

// ---------------------------------------------------------------------------
// Weight prep: fold BN + rotation + (stage1) channel-roll perm; emit fp16
// B-fragments packed so one LDS.128 serves an nt-pair:
//   word idx e = ((tap*4 + k16)*4 + np)*128 + lane*4 + half*2 + r
//   nt = np*2 + half; halves = W[oc = nt*8 + lane/4]
//                              [ic = k16*16 + 2*(lane%4) + 8r + {0,1}]
// ---------------------------------------------------------------------------
__global__ void prep_kernel(
    const float* __restrict__ dcn_w, const float* __restrict__ dcn_b,
    const float* __restrict__ c2w,   const float* __restrict__ c2b,
    const float* __restrict__ c3w,   const float* __restrict__ c3b,
    const float* __restrict__ gam,   const float* __restrict__ bet,
    const float* __restrict__ mu,    const float* __restrict__ va)
{
    int id = blockIdx.x * blockDim.x + threadIdx.x;
    const int W1N = 8 * WSETW, W2N = 4 * WSETW;

    if (id < W1N + 2 * W2N) {
        int setBase;
        uint32_t* dst;
        const float* src;
        int bnOff;
        if (id < W1N)            { dst = g_w1; src = dcn_w; bnOff = 0;   setBase = id; }
        else if (id < W1N + W2N) { dst = g_w2; src = c2w;   bnOff = 64;  setBase = id - W1N; }
        else                     { dst = g_w3; src = c3w;   bnOff = 128; setBase = id - W1N - W2N; }
        int set = setBase / WSETW;
        int e   = setBase % WSETW;
        int r    = e & 1;
        int half = (e >> 1) & 1;
        int lane = (e >> 2) & 31;
        int np   = (e >> 7) & 3;
        int k16  = (e >> 9) & 3;
        int tap  = e >> 11;            // 0..8
        int nt = np * 2 + half;
        int oc  = nt * 8 + (lane >> 2);
        int ic0 = k16 * 16 + 2 * (lane & 3) + 8 * r;
        int sa, sb; rotmap(set & 3, tap / 3, tap % 3, sa, sb);
        float scale = gam[bnOff + oc] * rsqrtf(va[bnOff + oc] + 1e-5f);
        int sc0 = (bnOff == 0) ? ((ic0 + 8 * set) & 63) : ic0;
        int sc1 = (bnOff == 0) ? ((ic0 + 1 + 8 * set) & 63) : (ic0 + 1);
        float v0 = src[((oc * 64 + sc0) * 3 + sa) * 3 + sb] * scale;
        float v1 = src[((oc * 64 + sc1) * 3 + sa) * 3 + sb] * scale;
        uint32_t w = (uint32_t)__half_as_ushort(__float2half(v0))
                   | ((uint32_t)__half_as_ushort(__float2half(v1)) << 16);
        dst[setBase] = w;
        return;
    }
    id -= W1N + 2 * W2N;
    if (id < 192) {
        int s = id / 64, oc = id & 63;
        float scale = gam[s * 64 + oc] * rsqrtf(va[s * 64 + oc] + 1e-5f);
        const float* cb = (s == 0) ? dcn_b : ((s == 1) ? c2b : c3b);
        g_bias[id] = cb[oc] * scale + bet[s * 64 + oc] - mu[s * 64 + oc] * scale;
    }
}

// ---------------------------------------------------------------------------
// Conv kernel: fp16 mma.sync.m16n8k16 implicit GEMM, 1.0 smem-wf/HMMA.
// Block = 256 threads = 8 warps (warpM = wid, rows 2w..2w+1). 1 CTA/SM.
// CTA tile = 16 rows x 32 cols = 512 px. Warp tile = 64 px x 64 oc:
// mt = (mtr, mtc): m16 group = row (2w+mtr), cols mtc*16 + 0..15.
// Per k16: 4 LDSM.x4 (A, 2048B) + 4 LDS.128 (B, 2048B) -> 32 HMMA.
// Patch loaded via cp.async (zfill OOB).
// ---------------------------------------------------------------------------
template<int D, int STAGE>
__global__ void __launch_bounds__(256, 1)
conv_mma()
{
    constexpr int R = 16 + 2 * D;         // patch rows
    constexpr int C = 32 + 2 * D;         // patch cols
    constexpr int NPIX = R * C;

    extern __shared__ char sm[];
    uint32_t* sW    = (uint32_t*)sm;                      // 73728B
    __half*   sIn   = (__half*)(sm + 73728);              // NPIX * 144B
    float*    sBias = (float*)(sm + 73728 + NPIX * PIXB); // 64

    const int tid  = threadIdx.x;
    const int lane = tid & 31;
    const int wid  = tid >> 5;            // warpM 0..7

    const int br = blockIdx.z;
    const int b  = blockIdx.y;
    const int odd = br & 1;

    int pad, inValid, outH;
    if (STAGE == 1)      { pad = odd ? 5 : 1; inValid = 96;             outH = odd ? 104 : 96; }
    else if (STAGE == 2) { pad = odd ? 0 : 2; inValid = odd ? 104 : 96; outH = odd ? 100 : 96; }
    else                 { pad = odd ? 0 : 2; inValid = odd ? 100 : 96; outH = 96; }
    const int outW = outH;
    const int rowTiles = (outH + 15) >> 4;
    const int colTiles = (outW + 31) >> 5;
    const int rowTile = blockIdx.x;
    if (rowTile >= rowTiles) return;      // uniform per block

    const int srcStride = (STAGE == 1) ? MAPH : BSTR;
    const __half* inp = (STAGE == 1) ? (g_x16 + (size_t)b * MAPH * MAPH * NCH)
                       : (STAGE == 2) ? (g_buf1 + (size_t)(br * NBATCH + b) * BCHS * NCH)
                                      : (g_buf2 + (size_t)(br * NBATCH + b) * BCHS * NCH);
    __half* outp = ((STAGE == 1) ? g_buf1 : g_buf2)
                   + (size_t)(br * NBATCH + b) * BCHS * NCH;
    const uint32_t* wsrc = (STAGE == 1) ? (g_w1 + br * WSETW)
                          : (STAGE == 2) ? (g_w2 + (br & 3) * WSETW)
                                         : (g_w3 + (br & 3) * WSETW);

    // ---- stage weights (fragment words, linear copy) + bias ----
    {
        uint4* wd = (uint4*)sW;
        const uint4* ws = (const uint4*)wsrc;
        #pragma unroll 4
        for (int i = tid; i < WSETW / 4; i += 256) wd[i] = ws[i];
        if (tid < 64) sBias[tid] = g_bias[(STAGE - 1) * 64 + tid];
    }

    const int rowBase = rowTile * 16;
    const int g  = lane >> 2;
    const int t4 = lane & 3;

    // ldmatrix per-lane base: pixel col = lane&15, k-half-block = lane>>4
    const uint32_t sInU = smem_u32(sIn);
    const uint32_t aLane = sInU + ((wid * 2) * C + (lane & 15)) * PIXB + (lane >> 4) * 16;

    const uint4* srcV = (const uint4*)inp;

    for (int ct = 0; ct < colTiles; ct++) {
        const int colBase = ct * 32;
        __syncthreads();   // prior-iter reads of sIn done before overwrite

        // ---- patch via cp.async: 8 x 16B per pixel, zfill OOB ----
        for (int i = tid; i < NPIX * 8; i += 256) {
            int w   = i & 7;
            int pix = i >> 3;
            int r = pix / C;
            int c = pix - r * C;
            int gy = rowBase + r - pad;
            int gx = colBase + c - pad;
            bool ok = ((unsigned)gy < (unsigned)inValid) & ((unsigned)gx < (unsigned)inValid);
            const void* gp = ok ? (const void*)(srcV + (size_t)(gy * srcStride + gx) * 8 + w)
                                : (const void*)srcV;
            cp_async16(sInU + pix * PIXB + w * 16, gp, ok ? 16 : 0);
        }
        asm volatile("cp.async.commit_group;" ::: "memory");
        asm volatile("cp.async.wait_group 0;" ::: "memory");
        __syncthreads();

        // ---- GEMM: 512px x 64oc x 576; warp = 64px x 64oc ----
        float acc[4][8][4];
        #pragma unroll
        for (int mt = 0; mt < 4; mt++)
            #pragma unroll
            for (int nt = 0; nt < 8; nt++)
                #pragma unroll
                for (int q = 0; q < 4; q++) acc[mt][nt][q] = 0.f;

        #pragma unroll 1
        for (int tap = 0; tap < 9; tap++) {
            const int dy = (tap / 3) * D, dx = (tap % 3) * D;
            const uint32_t aT = aLane + (dy * C + dx) * PIXB;

            #pragma unroll
            for (int k16 = 0; k16 < 4; k16++) {
                uint32_t a[4][4];
                #pragma unroll
                for (int mtr = 0; mtr < 2; mtr++)
                    #pragma unroll
                    for (int mtc = 0; mtc < 2; mtc++)
                        ldmatrix_x4(a[mtr * 2 + mtc][0], a[mtr * 2 + mtc][1],
                                    a[mtr * 2 + mtc][2], a[mtr * 2 + mtc][3],
                                    aT + (mtr * C + mtc * 16) * PIXB + k16 * 32);
                const uint4* pB = (const uint4*)sW + (tap * 16 + k16 * 4) * 32 + lane;
                #pragma unroll
                for (int np = 0; np < 4; np++) {
                    uint4 bb = pB[np * 32];
                    #pragma unroll
                    for (int mt = 0; mt < 4; mt++) {
                        mma_f16(acc[mt][2*np][0], acc[mt][2*np][1],
                                acc[mt][2*np][2], acc[mt][2*np][3],
                                a[mt][0], a[mt][1], a[mt][2], a[mt][3], bb.x, bb.y);
                        mma_f16(acc[mt][2*np+1][0], acc[mt][2*np+1][1],
                                acc[mt][2*np+1][2], acc[mt][2*np+1][3],
                                a[mt][0], a[mt][1], a[mt][2], a[mt][3], bb.z, bb.w);
                    }
                }
            }
        }

        // ---- epilogue (warp owns all 64 oc of its 64 pixels) ----
        if (STAGE < 3) {
            #pragma unroll
            for (int mtr = 0; mtr < 2; mtr++) {
                const int oy = rowBase + wid * 2 + mtr;
                if (oy >= outH) continue;
                #pragma unroll
                for (int mtc = 0; mtc < 2; mtc++) {
                    const int mt = mtr * 2 + mtc;
                    const int ox0 = colBase + mtc * 16 + g;
                    const int ox1 = ox0 + 8;
                    #pragma unroll
                    for (int nt = 0; nt < 8; nt++) {
                        const int oc = nt * 8 + 2 * t4;
                        const float b0 = sBias[oc], b1 = sBias[oc + 1];
                        if (ox0 < outW) {
                            float2 f = make_float2(fmaxf(acc[mt][nt][0] + b0, 0.f),
                                                   fmaxf(acc[mt][nt][1] + b1, 0.f));
                            *(__half2*)(outp + (size_t)(oy * BSTR + ox0) * 64 + oc) =
                                __float22half2_rn(f);
                        }
                        if (ox1 < outW) {
                            float2 f = make_float2(fmaxf(acc[mt][nt][2] + b0, 0.f),
                                                   fmaxf(acc[mt][nt][3] + b1, 0.f));
                            *(__half2*)(outp + (size_t)(oy * BSTR + ox1) * 64 + oc) =
                                __float22half2_rn(f);
                        }
                    }
                }
            }
        } else {
            // bias + relu + channel-max in-warp; stage3 tiling exact (96 = 6x16, 3x32)
            float* bm = g_bmax + (size_t)(br * NBATCH + b) * MAPH * MAPH;
            #pragma unroll
            for (int mtr = 0; mtr < 2; mtr++) {
                const int oy = rowBase + wid * 2 + mtr;
                #pragma unroll
                for (int mtc = 0; mtc < 2; mtc++) {
                    const int mt = mtr * 2 + mtc;
                    float v0 = 0.f, v1 = 0.f;
                    #pragma unroll
                    for (int nt = 0; nt < 8; nt++) {
                        const int oc = nt * 8 + 2 * t4;
                        const float b0 = sBias[oc], b1 = sBias[oc + 1];
                        v0 = fmaxf(v0, fmaxf(acc[mt][nt][0] + b0, acc[mt][nt][1] + b1));
                        v1 = fmaxf(v1, fmaxf(acc[mt][nt][2] + b0, acc[mt][nt][3] + b1));
                    }
                    v0 = fmaxf(v0, __shfl_xor_sync(0xFFFFFFFF, v0, 1));
                    v0 = fmaxf(v0, __shfl_xor_sync(0xFFFFFFFF, v0, 2));
                    v1 = fmaxf(v1, __shfl_xor_sync(0xFFFFFFFF, v1, 1));
                    v1 = fmaxf(v1, __shfl_xor_sync(0xFFFFFFFF, v1, 2));
                    if (t4 == 0) {
                        bm[oy * MAPH + colBase + mtc * 16 + g]     = v0;
                        bm[oy * MAPH + colBase + mtc * 16 + g + 8] = v1;
                    }
                }
            }
        }
    }
}

// ---------------------------------------------------------------------------
// Cross-branch max + sigmoid + clip
// ---------------------------------------------------------------------------
__global__ void final_k(float* __restrict__ out)
{
    int i = blockIdx.x * blockDim.x + threadIdx.x;
    const int NPB = MAPH * MAPH;
    if (i >= NBATCH * NPB) return;
    int b = i / NPB, p = i - b * NPB;
    float m = g_bmax[b * NPB + p];
    #pragma unroll
    for (int br = 1; br < NBR; br++)
        m = fmaxf(m, g_bmax[(br * NBATCH + b) * NPB + p]);
    float s = 1.f / (1.f + expf(-m));
    out[i] = fminf(fmaxf(s, 0.0001f), 0.9999f);
}

// ---------------------------------------------------------------------------
// Launch
// ---------------------------------------------------------------------------
extern "C" void kernel_launch(void* const* d_in, const int* in_sizes, int n_in,
                              void* d_out, int out_size)
{
    const float* x     = (const float*)d_in[0];
    const float* dcn_w = (const float*)d_in[2];
    const float* dcn_b = (const float*)d_in[3];
    const float* c2w   = (const float*)d_in[4];
    const float* c2b   = (const float*)d_in[5];
    const float* c3w   = (const float*)d_in[6];
    const float* c3b   = (const float*)d_in[7];
    const float* gam   = (const float*)d_in[8];
    const float* bet   = (const float*)d_in[9];
    const float* mu    = (const float*)d_in[10];
    const float* va    = (const float*)d_in[11];

    constexpr int SMEM_D1 = 73728 + 18 * 34 * PIXB + 64 * 4;  // 162,112
    constexpr int SMEM_D2 = 73728 + 20 * 36 * PIXB + 64 * 4;  // 177,664

    cudaFuncSetAttribute((const void*)conv_mma<1, 1>,
                         cudaFuncAttributeMaxDynamicSharedMemorySize, SMEM_D1);
    cudaFuncSetAttribute((const void*)conv_mma<2, 2>,
                         cudaFuncAttributeMaxDynamicSharedMemorySize, SMEM_D2);
    cudaFuncSetAttribute((const void*)conv_mma<2, 3>,
                         cudaFuncAttributeMaxDynamicSharedMemorySize, SMEM_D2);

    cvt_x<<<NBATCH * (MAPH * MAPH / 64), 256>>>(x);

    const int prepN = 16 * WSETW + 192;
    prep_kernel<<<(prepN + 255) / 256, 256>>>(dcn_w, dcn_b, c2w, c2b, c3w, c3b,
                                              gam, bet, mu, va);

    // Stage 1 (D=1): even 96->96 (pad1, 6x3 tiles), odd 96->104 (7x4). grid.x=7
    conv_mma<1, 1><<<dim3(7, NBATCH, NBR), 256, SMEM_D1>>>();
    // Stage 2 (D=2): even 96->96 (6x3), odd 104->100 (7x4). grid.x=7
    conv_mma<2, 2><<<dim3(7, NBATCH, NBR), 256, SMEM_D2>>>();
    // Stage 3 (D=2) + channel max: 96 out exact (6x3). grid.x=6
    conv_mma<2, 3><<<dim3(6, NBATCH, NBR), 256, SMEM_D2>>>();

    final_k<<<(NBATCH * MAPH * MAPH + 255) / 256, 256>>>((float*)d_out);
}